// round 1
// baseline (speedup 1.0000x reference)
#include <cuda_runtime.h>
#include <math.h>

// Problem constants (hardcoded from reference: B=2, S=2048, D=1024, H=16, Dk=64)
#define BATCH   2
#define SEQ     2048
#define DMODEL  1024
#define NHEAD   16
#define DK      64
#define MROWS   (BATCH * SEQ)   // 4096

// Scratch (allocation-free rule: __device__ globals). 4 x 16 MB.
__device__ float g_Q[MROWS * DMODEL];
__device__ float g_K[MROWS * DMODEL];
__device__ float g_V[MROWS * DMODEL];
__device__ float g_A[MROWS * DMODEL];

// ---------------------------------------------------------------------------
// Tiled SGEMM with bias: C[M,N] = A[M,K] @ W[K,N] + bias[N]
// BM=BN=128, BK=8, 256 threads, 8x8 per-thread microtile.
// M=4096, N=1024, K=1024 -> all tiles exact, no bounds checks.
// ---------------------------------------------------------------------------
__global__ __launch_bounds__(256) void sgemm_bias(
    const float* __restrict__ A, const float* __restrict__ W,
    const float* __restrict__ bias, float* __restrict__ C,
    int M, int N, int K)
{
    const int BM = 128, BN = 128, BK = 8;
    __shared__ __align__(16) float As[BK][BM];
    __shared__ __align__(16) float Bs[BK][BN];

    const int tid = threadIdx.x;
    const int tx = tid & 15;        // 0..15 -> N direction
    const int ty = tid >> 4;        // 0..15 -> M direction

    const int aRow = tid >> 1;          // 0..127
    const int aCol = (tid & 1) << 2;    // 0 or 4
    const int bRow = tid >> 5;          // 0..7
    const int bCol = (tid & 31) << 2;   // 0..124

    const float* Aptr = A + (size_t)(blockIdx.y * BM) * K;
    const float* Wptr = W + (size_t)(blockIdx.x * BN);

    float acc[8][8];
#pragma unroll
    for (int i = 0; i < 8; ++i)
#pragma unroll
        for (int j = 0; j < 8; ++j) acc[i][j] = 0.f;

    for (int k0 = 0; k0 < K; k0 += BK) {
        float4 av = *(const float4*)(Aptr + (size_t)aRow * K + k0 + aCol);
        As[aCol + 0][aRow] = av.x;
        As[aCol + 1][aRow] = av.y;
        As[aCol + 2][aRow] = av.z;
        As[aCol + 3][aRow] = av.w;
        float4 bv = *(const float4*)(Wptr + (size_t)(k0 + bRow) * N + bCol);
        *(float4*)&Bs[bRow][bCol] = bv;
        __syncthreads();

#pragma unroll
        for (int k = 0; k < BK; ++k) {
            float4 a0 = *(const float4*)&As[k][ty * 8];
            float4 a1 = *(const float4*)&As[k][ty * 8 + 4];
            float4 b0 = *(const float4*)&Bs[k][tx * 8];
            float4 b1 = *(const float4*)&Bs[k][tx * 8 + 4];
            float ar[8] = {a0.x, a0.y, a0.z, a0.w, a1.x, a1.y, a1.z, a1.w};
            float br[8] = {b0.x, b0.y, b0.z, b0.w, b1.x, b1.y, b1.z, b1.w};
#pragma unroll
            for (int i = 0; i < 8; ++i)
#pragma unroll
                for (int j = 0; j < 8; ++j)
                    acc[i][j] += ar[i] * br[j];
        }
        __syncthreads();
    }

    // Epilogue: add bias, write C
    const int rowBase = blockIdx.y * BM + ty * 8;
    const int colBase = blockIdx.x * BN + tx * 8;
#pragma unroll
    for (int i = 0; i < 8; ++i) {
        float* crow = C + (size_t)(rowBase + i) * N + colBase;
#pragma unroll
        for (int j = 0; j < 8; j += 4) {
            float4 o;
            o.x = acc[i][j + 0] + bias[colBase + j + 0];
            o.y = acc[i][j + 1] + bias[colBase + j + 1];
            o.z = acc[i][j + 2] + bias[colBase + j + 2];
            o.w = acc[i][j + 3] + bias[colBase + j + 3];
            *(float4*)(crow + j) = o;
        }
    }
}

// ---------------------------------------------------------------------------
// Flash-style attention, fp32. Q/K/V in [B*S, DMODEL] layout, head h at
// column offset h*DK. Per block: one (b,h) pair + 64 query rows; loop over
// 32 key tiles of 64 with online softmax.
// Thread map: tx = tid&15 (key cols, stride 16), ty = tid>>4 (q rows, stride 16),
// each thread owns a 4x4 microtile. Row reductions via 16-lane shfl butterfly.
// ---------------------------------------------------------------------------
#define ATT_SMEM (4 * 64 * 65 * 4)   // Qs,Ks,Vs,Ps each [64][65] floats

__global__ __launch_bounds__(256) void flash_attn(
    const float* __restrict__ Qg, const float* __restrict__ Kg,
    const float* __restrict__ Vg, float* __restrict__ Og)
{
    extern __shared__ float sm[];
    float* Qs = sm;                 // Qs[d*65 + r]   (transposed, pre-scaled)
    float* Ks = sm + 64 * 65;       // Ks[d*65 + c]   (transposed)
    float* Vs = sm + 2 * 64 * 65;   // Vs[k*65 + c]
    float* Ps = sm + 3 * 64 * 65;   // Ps[r*65 + k]

    const int tid = threadIdx.x;
    const int tx = tid & 15;
    const int ty = tid >> 4;
    const int bh = blockIdx.y;
    const int b = bh >> 4, h = bh & 15;
    const int q0 = blockIdx.x * 64;

    const float* Qb = Qg + ((size_t)(b * SEQ + q0)) * DMODEL + h * DK;

    // Load Q tile transposed, folding in the 1/sqrt(Dk) scale.
#pragma unroll
    for (int t = 0; t < 4; ++t) {
        int idx = tid + t * 256;
        int r = idx >> 4;
        int c4 = (idx & 15) << 2;
        float4 qv = *(const float4*)(Qb + (size_t)r * DMODEL + c4);
        Qs[(c4 + 0) * 65 + r] = qv.x * 0.125f;
        Qs[(c4 + 1) * 65 + r] = qv.y * 0.125f;
        Qs[(c4 + 2) * 65 + r] = qv.z * 0.125f;
        Qs[(c4 + 3) * 65 + r] = qv.w * 0.125f;
    }

    float m[4], l[4], o[4][4];
#pragma unroll
    for (int i = 0; i < 4; ++i) {
        m[i] = -INFINITY; l[i] = 0.f;
#pragma unroll
        for (int j = 0; j < 4; ++j) o[i][j] = 0.f;
    }
    __syncthreads();

    for (int k0 = 0; k0 < SEQ; k0 += 64) {
        const float* Kb = Kg + ((size_t)(b * SEQ + k0)) * DMODEL + h * DK;
        const float* Vb = Vg + ((size_t)(b * SEQ + k0)) * DMODEL + h * DK;
#pragma unroll
        for (int t = 0; t < 4; ++t) {
            int idx = tid + t * 256;
            int r = idx >> 4;
            int c4 = (idx & 15) << 2;
            float4 kv = *(const float4*)(Kb + (size_t)r * DMODEL + c4);
            Ks[(c4 + 0) * 65 + r] = kv.x;
            Ks[(c4 + 1) * 65 + r] = kv.y;
            Ks[(c4 + 2) * 65 + r] = kv.z;
            Ks[(c4 + 3) * 65 + r] = kv.w;
            float4 vv = *(const float4*)(Vb + (size_t)r * DMODEL + c4);
            Vs[r * 65 + c4 + 0] = vv.x;
            Vs[r * 65 + c4 + 1] = vv.y;
            Vs[r * 65 + c4 + 2] = vv.z;
            Vs[r * 65 + c4 + 3] = vv.w;
        }
        __syncthreads();

        // S = Q @ K^T  (scaled)
        float s[4][4];
#pragma unroll
        for (int i = 0; i < 4; ++i)
#pragma unroll
            for (int j = 0; j < 4; ++j) s[i][j] = 0.f;

#pragma unroll 8
        for (int d = 0; d < 64; ++d) {
            float qr[4], kr[4];
#pragma unroll
            for (int i = 0; i < 4; ++i) qr[i] = Qs[d * 65 + ty + i * 16];
#pragma unroll
            for (int j = 0; j < 4; ++j) kr[j] = Ks[d * 65 + tx + j * 16];
#pragma unroll
            for (int i = 0; i < 4; ++i)
#pragma unroll
                for (int j = 0; j < 4; ++j) s[i][j] += qr[i] * kr[j];
        }

        // Online softmax per query row (reduce over 16 tx lanes)
#pragma unroll
        for (int i = 0; i < 4; ++i) {
            float mx = s[i][0];
#pragma unroll
            for (int j = 1; j < 4; ++j) mx = fmaxf(mx, s[i][j]);
#pragma unroll
            for (int w = 1; w < 16; w <<= 1)
                mx = fmaxf(mx, __shfl_xor_sync(0xffffffffu, mx, w));
            float mn = fmaxf(m[i], mx);
            float corr = __expf(m[i] - mn);
            float rs = 0.f;
#pragma unroll
            for (int j = 0; j < 4; ++j) {
                s[i][j] = __expf(s[i][j] - mn);
                rs += s[i][j];
            }
#pragma unroll
            for (int w = 1; w < 16; w <<= 1)
                rs += __shfl_xor_sync(0xffffffffu, rs, w);
            l[i] = l[i] * corr + rs;
            m[i] = mn;
#pragma unroll
            for (int j = 0; j < 4; ++j) o[i][j] *= corr;
        }

        // Stage P (conflict-free: lanes vary tx -> stride 1)
#pragma unroll
        for (int i = 0; i < 4; ++i)
#pragma unroll
            for (int j = 0; j < 4; ++j)
                Ps[(ty + i * 16) * 65 + tx + j * 16] = s[i][j];
        __syncthreads();

        // O += P @ V
#pragma unroll 8
        for (int kk = 0; kk < 64; ++kk) {
            float pr[4], vr[4];
#pragma unroll
            for (int i = 0; i < 4; ++i) pr[i] = Ps[(ty + i * 16) * 65 + kk];
#pragma unroll
            for (int j = 0; j < 4; ++j) vr[j] = Vs[kk * 65 + tx + j * 16];
#pragma unroll
            for (int i = 0; i < 4; ++i)
#pragma unroll
                for (int j = 0; j < 4; ++j) o[i][j] += pr[i] * vr[j];
        }
        __syncthreads();
    }

    // Normalize and write out in [B, S, H*Dk] layout
    float* Ob = Og + ((size_t)(b * SEQ + q0)) * DMODEL + h * DK;
#pragma unroll
    for (int i = 0; i < 4; ++i) {
        float inv = 1.f / l[i];
#pragma unroll
        for (int j = 0; j < 4; ++j)
            Ob[(size_t)(ty + i * 16) * DMODEL + tx + j * 16] = o[i][j] * inv;
    }
}

// ---------------------------------------------------------------------------
extern "C" void kernel_launch(void* const* d_in, const int* in_sizes, int n_in,
                              void* d_out, int out_size)
{
    const float* x  = (const float*)d_in[0];
    const float* Wq = (const float*)d_in[1];
    const float* bq = (const float*)d_in[2];
    const float* Wk = (const float*)d_in[3];
    const float* bk = (const float*)d_in[4];
    const float* Wv = (const float*)d_in[5];
    const float* bv = (const float*)d_in[6];
    const float* Wo = (const float*)d_in[7];
    const float* bo = (const float*)d_in[8];
    float* out = (float*)d_out;

    float *q, *k, *v, *a;
    cudaGetSymbolAddress((void**)&q, g_Q);
    cudaGetSymbolAddress((void**)&k, g_K);
    cudaGetSymbolAddress((void**)&v, g_V);
    cudaGetSymbolAddress((void**)&a, g_A);

    cudaFuncSetAttribute(flash_attn,
                         cudaFuncAttributeMaxDynamicSharedMemorySize, ATT_SMEM);

    dim3 gemmGrid(DMODEL / 128, MROWS / 128);   // (8, 32)
    sgemm_bias<<<gemmGrid, 256>>>(x, Wq, bq, q, MROWS, DMODEL, DMODEL);
    sgemm_bias<<<gemmGrid, 256>>>(x, Wk, bk, k, MROWS, DMODEL, DMODEL);
    sgemm_bias<<<gemmGrid, 256>>>(x, Wv, bv, v, MROWS, DMODEL, DMODEL);

    dim3 attGrid(SEQ / 64, BATCH * NHEAD);      // (32, 32)
    flash_attn<<<attGrid, 256, ATT_SMEM>>>(q, k, v, a);

    sgemm_bias<<<gemmGrid, 256>>>(a, Wo, bo, out, MROWS, DMODEL, DMODEL);
}

// round 2
// speedup vs baseline: 2.0827x; 2.0827x over previous
#include <cuda_runtime.h>
#include <math.h>

// Problem constants: B=2, S=2048, D=1024, H=16, Dk=64
#define BATCH   2
#define SEQ     2048
#define DMODEL  1024
#define NHEAD   16
#define DK      64
#define MROWS   (BATCH * SEQ)   // 4096

// Scratch (allocation-free rule): __device__ globals, 4 x 16 MB.
__device__ float g_Q[MROWS * DMODEL];
__device__ float g_K[MROWS * DMODEL];
__device__ float g_V[MROWS * DMODEL];
__device__ float g_A[MROWS * DMODEL];

// ---------------------------------------------------------------------------
// tf32 helpers
// ---------------------------------------------------------------------------
__device__ __forceinline__ unsigned f2tf(float f) {
    unsigned u;
    asm("cvt.rna.tf32.f32 %0, %1;" : "=r"(u) : "f"(f));
    return u;
}

// D = A(16x8) @ B(8x8) + D, tf32 inputs, fp32 accum.
__device__ __forceinline__ void mma8(float* c,
                                     unsigned a0, unsigned a1, unsigned a2, unsigned a3,
                                     unsigned b0, unsigned b1) {
    asm volatile(
        "mma.sync.aligned.m16n8k8.row.col.f32.tf32.tf32.f32 "
        "{%0,%1,%2,%3},{%4,%5,%6,%7},{%8,%9},{%0,%1,%2,%3};"
        : "+f"(c[0]), "+f"(c[1]), "+f"(c[2]), "+f"(c[3])
        : "r"(a0), "r"(a1), "r"(a2), "r"(a3), "r"(b0), "r"(b1));
}

// ---------------------------------------------------------------------------
// Tensor-core GEMM: C[M,N] = A[M,K] @ W[K,N] + bias[N]
// Block 128x128, BK=32, 256 threads = 8 warps (4 in M x 2 in N).
// Warp tile 32x64 -> 2 (m16) x 8 (n8) mma tiles per k-step of 8.
// Padding: As stride 36 (==4 mod 32), Ws stride 136 (==8 mod 32):
// fragment reads are bank-conflict-free.
// ---------------------------------------------------------------------------
#define AS_LD 36
#define WS_LD 136

__global__ __launch_bounds__(256) void gemm_tc(
    const float* __restrict__ A, const float* __restrict__ W,
    const float* __restrict__ bias, float* __restrict__ C,
    int M, int N, int K)
{
    __shared__ unsigned As[128 * AS_LD];
    __shared__ unsigned Ws[32 * WS_LD];

    const int tid = threadIdx.x;
    const int lane = tid & 31;
    const int warp = tid >> 5;
    const int wm = (warp & 3) * 32;       // warp M offset within block
    const int wn = (warp >> 2) * 64;      // warp N offset within block
    const int m0 = blockIdx.y * 128;
    const int n0 = blockIdx.x * 128;

    const float* Ap = A + (size_t)m0 * K;

    float acc[2][8][4];
#pragma unroll
    for (int mt = 0; mt < 2; ++mt)
#pragma unroll
        for (int nt = 0; nt < 8; ++nt)
#pragma unroll
            for (int i = 0; i < 4; ++i) acc[mt][nt][i] = 0.f;

    for (int k0 = 0; k0 < K; k0 += 32) {
        // Stage A tile 128x32 (cvt to tf32 on store)
#pragma unroll
        for (int p = 0; p < 4; ++p) {
            int r = (tid >> 3) + p * 32;
            int c = (tid & 7) * 4;
            float4 v = *(const float4*)(Ap + (size_t)r * K + k0 + c);
            unsigned* d = &As[r * AS_LD + c];
            d[0] = f2tf(v.x); d[1] = f2tf(v.y); d[2] = f2tf(v.z); d[3] = f2tf(v.w);
        }
        // Stage W tile 32x128
#pragma unroll
        for (int p = 0; p < 4; ++p) {
            int r = (tid >> 5) + p * 8;
            int c = (tid & 31) * 4;
            float4 v = *(const float4*)(W + (size_t)(k0 + r) * N + n0 + c);
            unsigned* d = &Ws[r * WS_LD + c];
            d[0] = f2tf(v.x); d[1] = f2tf(v.y); d[2] = f2tf(v.z); d[3] = f2tf(v.w);
        }
        __syncthreads();

#pragma unroll
        for (int kk = 0; kk < 4; ++kk) {
            unsigned a[2][4];
#pragma unroll
            for (int mt = 0; mt < 2; ++mt) {
                int r = wm + mt * 16 + (lane >> 2);
                int c = kk * 8 + (lane & 3);
                a[mt][0] = As[r * AS_LD + c];
                a[mt][1] = As[(r + 8) * AS_LD + c];
                a[mt][2] = As[r * AS_LD + c + 4];
                a[mt][3] = As[(r + 8) * AS_LD + c + 4];
            }
#pragma unroll
            for (int nt = 0; nt < 8; ++nt) {
                int kr = kk * 8 + (lane & 3);
                int cc = wn + nt * 8 + (lane >> 2);
                unsigned b0 = Ws[kr * WS_LD + cc];
                unsigned b1 = Ws[(kr + 4) * WS_LD + cc];
                mma8(acc[0][nt], a[0][0], a[0][1], a[0][2], a[0][3], b0, b1);
                mma8(acc[1][nt], a[1][0], a[1][1], a[1][2], a[1][3], b0, b1);
            }
        }
        __syncthreads();
    }

    // Epilogue: bias + store (float2 per row-pair)
#pragma unroll
    for (int mt = 0; mt < 2; ++mt) {
#pragma unroll
        for (int nt = 0; nt < 8; ++nt) {
            int row = m0 + wm + mt * 16 + (lane >> 2);
            int col = n0 + wn + nt * 8 + 2 * (lane & 3);
            float bx = bias[col], by = bias[col + 1];
            float2 v0 = make_float2(acc[mt][nt][0] + bx, acc[mt][nt][1] + by);
            float2 v1 = make_float2(acc[mt][nt][2] + bx, acc[mt][nt][3] + by);
            *(float2*)(C + (size_t)row * N + col) = v0;
            *(float2*)(C + (size_t)(row + 8) * N + col) = v1;
        }
    }
}

// ---------------------------------------------------------------------------
// Flash attention with tf32 mma. 128 threads = 4 warps; each warp owns 16
// query rows of the 64-row q-block. Full Dk=64 kept in registers/smem.
// Online softmax in fp32 (exact). Row reductions live inside each 4-lane
// quad (shfl_xor 1,2) since a warp owns entire score rows.
// Padded strides: Qs/Ks/Ps 68 (==4 mod 32), Vs 72 (==8 mod 32) -> all
// fragment accesses bank-conflict-free.
// ---------------------------------------------------------------------------
#define QS_LD 68
#define KS_LD 68
#define VS_LD 72
#define PS_LD 68
#define ATT_SMEM ((64 * QS_LD + 64 * KS_LD + 64 * VS_LD + 64 * PS_LD) * 4)

__global__ __launch_bounds__(128) void attn_tc(
    const float* __restrict__ Qg, const float* __restrict__ Kg,
    const float* __restrict__ Vg, float* __restrict__ Og)
{
    extern __shared__ unsigned sm[];
    unsigned* Qs = sm;                       // [64][QS_LD]  (q rows x d), pre-scaled
    unsigned* Ks = Qs + 64 * QS_LD;          // [64][KS_LD]  (key rows x d)
    unsigned* Vs = Ks + 64 * KS_LD;          // [64][VS_LD]  (key rows x d)
    unsigned* Ps = Vs + 64 * VS_LD;          // [64][PS_LD]  (q rows x key)

    const int tid = threadIdx.x;
    const int lane = tid & 31;
    const int warp = tid >> 5;
    const int wr = warp * 16;                // warp's query-row base
    const int bh = blockIdx.y;
    const int b = bh >> 4, h = bh & 15;
    const int q0 = blockIdx.x * 64;

    const float* Qb = Qg + ((size_t)(b * SEQ + q0)) * DMODEL + h * DK;

    // Load Q tile (scale by 1/sqrt(Dk)=0.125, cvt tf32)
    {
        int r = tid >> 1;
        int cb = (tid & 1) * 32;
#pragma unroll
        for (int j = 0; j < 8; ++j) {
            float4 v = *(const float4*)(Qb + (size_t)r * DMODEL + cb + j * 4);
            unsigned* d = &Qs[r * QS_LD + cb + j * 4];
            d[0] = f2tf(v.x * 0.125f); d[1] = f2tf(v.y * 0.125f);
            d[2] = f2tf(v.z * 0.125f); d[3] = f2tf(v.w * 0.125f);
        }
    }

    float m0 = -INFINITY, m1 = -INFINITY, l0 = 0.f, l1 = 0.f;
    float o[8][4];
#pragma unroll
    for (int nt = 0; nt < 8; ++nt)
#pragma unroll
        for (int i = 0; i < 4; ++i) o[nt][i] = 0.f;

    for (int kt = 0; kt < SEQ; kt += 64) {
        const float* Kb = Kg + ((size_t)(b * SEQ + kt)) * DMODEL + h * DK;
        const float* Vb = Vg + ((size_t)(b * SEQ + kt)) * DMODEL + h * DK;
        {
            int r = tid >> 1;
            int cb = (tid & 1) * 32;
#pragma unroll
            for (int j = 0; j < 8; ++j) {
                float4 kv = *(const float4*)(Kb + (size_t)r * DMODEL + cb + j * 4);
                unsigned* dk = &Ks[r * KS_LD + cb + j * 4];
                dk[0] = f2tf(kv.x); dk[1] = f2tf(kv.y); dk[2] = f2tf(kv.z); dk[3] = f2tf(kv.w);
                float4 vv = *(const float4*)(Vb + (size_t)r * DMODEL + cb + j * 4);
                unsigned* dv = &Vs[r * VS_LD + cb + j * 4];
                dv[0] = f2tf(vv.x); dv[1] = f2tf(vv.y); dv[2] = f2tf(vv.z); dv[3] = f2tf(vv.w);
            }
        }
        __syncthreads();

        // S = Qs @ Ks^T  (warp: 16 x 64, k=64)
        float s[8][4];
#pragma unroll
        for (int nt = 0; nt < 8; ++nt)
#pragma unroll
            for (int i = 0; i < 4; ++i) s[nt][i] = 0.f;

#pragma unroll
        for (int kk = 0; kk < 8; ++kk) {
            int r = wr + (lane >> 2);
            int c = kk * 8 + (lane & 3);
            unsigned a0 = Qs[r * QS_LD + c];
            unsigned a1 = Qs[(r + 8) * QS_LD + c];
            unsigned a2 = Qs[r * QS_LD + c + 4];
            unsigned a3 = Qs[(r + 8) * QS_LD + c + 4];
#pragma unroll
            for (int nt = 0; nt < 8; ++nt) {
                int n = nt * 8 + (lane >> 2);
                unsigned b0 = Ks[n * KS_LD + kk * 8 + (lane & 3)];
                unsigned b1 = Ks[n * KS_LD + kk * 8 + (lane & 3) + 4];
                mma8(s[nt], a0, a1, a2, a3, b0, b1);
            }
        }

        // Online softmax (rows r0 = wr+lane/4, r1 = r0+8; each row spread
        // over the 4 lanes of a quad)
        float mx0 = -INFINITY, mx1 = -INFINITY;
#pragma unroll
        for (int nt = 0; nt < 8; ++nt) {
            mx0 = fmaxf(mx0, fmaxf(s[nt][0], s[nt][1]));
            mx1 = fmaxf(mx1, fmaxf(s[nt][2], s[nt][3]));
        }
        mx0 = fmaxf(mx0, __shfl_xor_sync(0xffffffffu, mx0, 1));
        mx0 = fmaxf(mx0, __shfl_xor_sync(0xffffffffu, mx0, 2));
        mx1 = fmaxf(mx1, __shfl_xor_sync(0xffffffffu, mx1, 1));
        mx1 = fmaxf(mx1, __shfl_xor_sync(0xffffffffu, mx1, 2));

        float mn0 = fmaxf(m0, mx0), mn1 = fmaxf(m1, mx1);
        float cr0 = __expf(m0 - mn0), cr1 = __expf(m1 - mn1);
        float su0 = 0.f, su1 = 0.f;
#pragma unroll
        for (int nt = 0; nt < 8; ++nt) {
            s[nt][0] = __expf(s[nt][0] - mn0); su0 += s[nt][0];
            s[nt][1] = __expf(s[nt][1] - mn0); su0 += s[nt][1];
            s[nt][2] = __expf(s[nt][2] - mn1); su1 += s[nt][2];
            s[nt][3] = __expf(s[nt][3] - mn1); su1 += s[nt][3];
        }
        su0 += __shfl_xor_sync(0xffffffffu, su0, 1);
        su0 += __shfl_xor_sync(0xffffffffu, su0, 2);
        su1 += __shfl_xor_sync(0xffffffffu, su1, 1);
        su1 += __shfl_xor_sync(0xffffffffu, su1, 2);

        l0 = l0 * cr0 + su0; m0 = mn0;
        l1 = l1 * cr1 + su1; m1 = mn1;
#pragma unroll
        for (int nt = 0; nt < 8; ++nt) {
            o[nt][0] *= cr0; o[nt][1] *= cr0;
            o[nt][2] *= cr1; o[nt][3] *= cr1;
        }

        // Stage P (C-frag layout -> smem -> A-frag layout), cvt tf32
#pragma unroll
        for (int nt = 0; nt < 8; ++nt) {
            int r = wr + (lane >> 2);
            int cc = nt * 8 + 2 * (lane & 3);
            Ps[r * PS_LD + cc]       = f2tf(s[nt][0]);
            Ps[r * PS_LD + cc + 1]   = f2tf(s[nt][1]);
            Ps[(r + 8) * PS_LD + cc]     = f2tf(s[nt][2]);
            Ps[(r + 8) * PS_LD + cc + 1] = f2tf(s[nt][3]);
        }
        __syncwarp();

        // O += P @ V   (warp: 16 x 64, k = 64 keys)
#pragma unroll
        for (int kk = 0; kk < 8; ++kk) {
            int r = wr + (lane >> 2);
            int c = kk * 8 + (lane & 3);
            unsigned a0 = Ps[r * PS_LD + c];
            unsigned a1 = Ps[(r + 8) * PS_LD + c];
            unsigned a2 = Ps[r * PS_LD + c + 4];
            unsigned a3 = Ps[(r + 8) * PS_LD + c + 4];
#pragma unroll
            for (int nt = 0; nt < 8; ++nt) {
                int kr = kk * 8 + (lane & 3);
                int cc = nt * 8 + (lane >> 2);
                unsigned b0 = Vs[kr * VS_LD + cc];
                unsigned b1 = Vs[(kr + 4) * VS_LD + cc];
                mma8(o[nt], a0, a1, a2, a3, b0, b1);
            }
        }
        __syncthreads();   // protect Ks/Vs before next tile's load
    }

    // Normalize, write out [B, S, H*Dk]
    float inv0 = 1.f / l0, inv1 = 1.f / l1;
    float* Ob = Og + ((size_t)(b * SEQ + q0)) * DMODEL + h * DK;
#pragma unroll
    for (int nt = 0; nt < 8; ++nt) {
        int r = wr + (lane >> 2);
        int cc = nt * 8 + 2 * (lane & 3);
        *(float2*)(Ob + (size_t)r * DMODEL + cc) =
            make_float2(o[nt][0] * inv0, o[nt][1] * inv0);
        *(float2*)(Ob + (size_t)(r + 8) * DMODEL + cc) =
            make_float2(o[nt][2] * inv1, o[nt][3] * inv1);
    }
}

// ---------------------------------------------------------------------------
extern "C" void kernel_launch(void* const* d_in, const int* in_sizes, int n_in,
                              void* d_out, int out_size)
{
    const float* x  = (const float*)d_in[0];
    const float* Wq = (const float*)d_in[1];
    const float* bq = (const float*)d_in[2];
    const float* Wk = (const float*)d_in[3];
    const float* bk = (const float*)d_in[4];
    const float* Wv = (const float*)d_in[5];
    const float* bv = (const float*)d_in[6];
    const float* Wo = (const float*)d_in[7];
    const float* bo = (const float*)d_in[8];
    float* out = (float*)d_out;

    float *q, *k, *v, *a;
    cudaGetSymbolAddress((void**)&q, g_Q);
    cudaGetSymbolAddress((void**)&k, g_K);
    cudaGetSymbolAddress((void**)&v, g_V);
    cudaGetSymbolAddress((void**)&a, g_A);

    cudaFuncSetAttribute(attn_tc,
                         cudaFuncAttributeMaxDynamicSharedMemorySize, ATT_SMEM);

    dim3 gemmGrid(DMODEL / 128, MROWS / 128);   // (8, 32)
    gemm_tc<<<gemmGrid, 256>>>(x, Wq, bq, q, MROWS, DMODEL, DMODEL);
    gemm_tc<<<gemmGrid, 256>>>(x, Wk, bk, k, MROWS, DMODEL, DMODEL);
    gemm_tc<<<gemmGrid, 256>>>(x, Wv, bv, v, MROWS, DMODEL, DMODEL);

    dim3 attGrid(SEQ / 64, BATCH * NHEAD);      // (32, 32)
    attn_tc<<<attGrid, 128, ATT_SMEM>>>(q, k, v, a);

    gemm_tc<<<gemmGrid, 256>>>(a, Wo, bo, out, MROWS, DMODEL, DMODEL);
}

// round 7
// speedup vs baseline: 2.2686x; 1.0893x over previous
#include <cuda_runtime.h>
#include <math.h>

// Problem constants: B=2, S=2048, D=1024, H=16, Dk=64
#define BATCH   2
#define SEQ     2048
#define DMODEL  1024
#define NHEAD   16
#define DK      64
#define MROWS   (BATCH * SEQ)   // 4096

// Scratch (allocation-free rule): __device__ globals, 4 x 16 MB.
__device__ float g_Q[MROWS * DMODEL];
__device__ float g_K[MROWS * DMODEL];
__device__ float g_V[MROWS * DMODEL];
__device__ float g_A[MROWS * DMODEL];

// ---------------------------------------------------------------------------
// tf32 helpers
// ---------------------------------------------------------------------------
__device__ __forceinline__ unsigned f2tf(float f) {
    unsigned u;
    asm("cvt.rna.tf32.f32 %0, %1;" : "=r"(u) : "f"(f));
    return u;
}

__device__ __forceinline__ void mma8(float* c,
                                     unsigned a0, unsigned a1, unsigned a2, unsigned a3,
                                     unsigned b0, unsigned b1) {
    asm volatile(
        "mma.sync.aligned.m16n8k8.row.col.f32.tf32.tf32.f32 "
        "{%0,%1,%2,%3},{%4,%5,%6,%7},{%8,%9},{%0,%1,%2,%3};"
        : "+f"(c[0]), "+f"(c[1]), "+f"(c[2]), "+f"(c[3])
        : "r"(a0), "r"(a1), "r"(a2), "r"(a3), "r"(b0), "r"(b1));
}

// ---------------------------------------------------------------------------
// Tensor-core GEMM with register-prefetch pipeline.
// C[M,N] = A[M,K] @ W[K,N] + bias[N]
// Block 128x128, BK=32, 256 threads = 8 warps (4 in M x 2 in N).
// ---------------------------------------------------------------------------
#define AS_LD 36
#define WS_LD 136

__global__ __launch_bounds__(256, 2) void gemm_tc(
    const float* __restrict__ A, const float* __restrict__ W,
    const float* __restrict__ bias, float* __restrict__ C,
    int M, int N, int K)
{
    __shared__ unsigned As[128 * AS_LD];
    __shared__ unsigned Ws[32 * WS_LD];

    const int tid = threadIdx.x;
    const int lane = tid & 31;
    const int warp = tid >> 5;
    const int wm = (warp & 3) * 32;
    const int wn = (warp >> 2) * 64;
    const int m0 = blockIdx.y * 128;
    const int n0 = blockIdx.x * 128;

    const float* Ap = A + (size_t)m0 * K;

    const int aRow = tid >> 3;            // 0..31 (+p*32)
    const int aCol = (tid & 7) * 4;
    const int wRow = tid >> 5;            // 0..7 (+p*8)
    const int wCol = (tid & 31) * 4;

    float acc[2][8][4];
#pragma unroll
    for (int mt = 0; mt < 2; ++mt)
#pragma unroll
        for (int nt = 0; nt < 8; ++nt)
#pragma unroll
            for (int i = 0; i < 4; ++i) acc[mt][nt][i] = 0.f;

    float4 aReg[4], wReg[4];
#pragma unroll
    for (int p = 0; p < 4; ++p) {
        aReg[p] = *(const float4*)(Ap + (size_t)(aRow + p * 32) * K + aCol);
        wReg[p] = *(const float4*)(W + (size_t)(wRow + p * 8) * N + n0 + wCol);
    }

    for (int k0 = 0; k0 < K; k0 += 32) {
        // Commit staged registers to smem (cvt tf32)
#pragma unroll
        for (int p = 0; p < 4; ++p) {
            unsigned* d = &As[(aRow + p * 32) * AS_LD + aCol];
            d[0] = f2tf(aReg[p].x); d[1] = f2tf(aReg[p].y);
            d[2] = f2tf(aReg[p].z); d[3] = f2tf(aReg[p].w);
            unsigned* e = &Ws[(wRow + p * 8) * WS_LD + wCol];
            e[0] = f2tf(wReg[p].x); e[1] = f2tf(wReg[p].y);
            e[2] = f2tf(wReg[p].z); e[3] = f2tf(wReg[p].w);
        }
        __syncthreads();

        // Prefetch next slab while computing this one
        if (k0 + 32 < K) {
#pragma unroll
            for (int p = 0; p < 4; ++p) {
                aReg[p] = *(const float4*)(Ap + (size_t)(aRow + p * 32) * K + k0 + 32 + aCol);
                wReg[p] = *(const float4*)(W + (size_t)(k0 + 32 + wRow + p * 8) * N + n0 + wCol);
            }
        }

#pragma unroll
        for (int kk = 0; kk < 4; ++kk) {
            unsigned a[2][4];
#pragma unroll
            for (int mt = 0; mt < 2; ++mt) {
                int r = wm + mt * 16 + (lane >> 2);
                int c = kk * 8 + (lane & 3);
                a[mt][0] = As[r * AS_LD + c];
                a[mt][1] = As[(r + 8) * AS_LD + c];
                a[mt][2] = As[r * AS_LD + c + 4];
                a[mt][3] = As[(r + 8) * AS_LD + c + 4];
            }
#pragma unroll
            for (int nt = 0; nt < 8; ++nt) {
                int kr = kk * 8 + (lane & 3);
                int cc = wn + nt * 8 + (lane >> 2);
                unsigned b0 = Ws[kr * WS_LD + cc];
                unsigned b1 = Ws[(kr + 4) * WS_LD + cc];
                mma8(acc[0][nt], a[0][0], a[0][1], a[0][2], a[0][3], b0, b1);
                mma8(acc[1][nt], a[1][0], a[1][1], a[1][2], a[1][3], b0, b1);
            }
        }
        __syncthreads();
    }

#pragma unroll
    for (int mt = 0; mt < 2; ++mt) {
#pragma unroll
        for (int nt = 0; nt < 8; ++nt) {
            int row = m0 + wm + mt * 16 + (lane >> 2);
            int col = n0 + wn + nt * 8 + 2 * (lane & 3);
            float bx = bias[col], by = bias[col + 1];
            float2 v0 = make_float2(acc[mt][nt][0] + bx, acc[mt][nt][1] + by);
            float2 v1 = make_float2(acc[mt][nt][2] + bx, acc[mt][nt][3] + by);
            *(float2*)(C + (size_t)row * N + col) = v0;
            *(float2*)(C + (size_t)(row + 8) * N + col) = v1;
        }
    }
}

// ---------------------------------------------------------------------------
// Flash attention, tf32 mma. 128 threads = 4 warps, 64-row q block,
// each warp owns 16 query rows.
// Q A-fragments held in registers (loaded once); the Qs smem buffer is
// reused as the P staging buffer in the mainloop -> 53KB/block -> 4 blocks/SM.
// ---------------------------------------------------------------------------
#define QS_LD 68
#define KS_LD 68
#define VS_LD 72
#define ATT_SMEM ((64 * QS_LD + 64 * KS_LD + 64 * VS_LD) * 4)

__global__ __launch_bounds__(128, 4) void attn_tc(
    const float* __restrict__ Qg, const float* __restrict__ Kg,
    const float* __restrict__ Vg, float* __restrict__ Og)
{
    extern __shared__ unsigned sm[];
    unsigned* Qs = sm;                       // [64][QS_LD]; becomes Ps after prologue
    unsigned* Ks = Qs + 64 * QS_LD;          // [64][KS_LD]
    unsigned* Vs = Ks + 64 * KS_LD;          // [64][VS_LD]
    unsigned* Ps = Qs;                       // alias

    const int tid = threadIdx.x;
    const int lane = tid & 31;
    const int warp = tid >> 5;
    const int wr = warp * 16;
    const int bh = blockIdx.y;
    const int b = bh >> 4, h = bh & 15;
    const int q0 = blockIdx.x * 64;

    const float* Qb = Qg + ((size_t)(b * SEQ + q0)) * DMODEL + h * DK;

    // Prologue: Q tile -> smem (scaled, tf32), then A-fragments -> registers.
    {
        int r = tid >> 1;
        int cb = (tid & 1) * 32;
#pragma unroll
        for (int j = 0; j < 8; ++j) {
            float4 v = *(const float4*)(Qb + (size_t)r * DMODEL + cb + j * 4);
            unsigned* d = &Qs[r * QS_LD + cb + j * 4];
            d[0] = f2tf(v.x * 0.125f); d[1] = f2tf(v.y * 0.125f);
            d[2] = f2tf(v.z * 0.125f); d[3] = f2tf(v.w * 0.125f);
        }
    }
    __syncthreads();

    unsigned qa[8][4];
#pragma unroll
    for (int kk = 0; kk < 8; ++kk) {
        int r = wr + (lane >> 2);
        int c = kk * 8 + (lane & 3);
        qa[kk][0] = Qs[r * QS_LD + c];
        qa[kk][1] = Qs[(r + 8) * QS_LD + c];
        qa[kk][2] = Qs[r * QS_LD + c + 4];
        qa[kk][3] = Qs[(r + 8) * QS_LD + c + 4];
    }
    // Note: barrier separating these reads from the first Ps store is the
    // __syncthreads after the first K/V stage below.

    float m0 = -INFINITY, m1 = -INFINITY, l0 = 0.f, l1 = 0.f;
    float o[8][4];
#pragma unroll
    for (int nt = 0; nt < 8; ++nt)
#pragma unroll
        for (int i = 0; i < 4; ++i) o[nt][i] = 0.f;

    for (int kt = 0; kt < SEQ; kt += 64) {
        const float* Kb = Kg + ((size_t)(b * SEQ + kt)) * DMODEL + h * DK;
        const float* Vb = Vg + ((size_t)(b * SEQ + kt)) * DMODEL + h * DK;
        {
            int r = tid >> 1;
            int cb = (tid & 1) * 32;
#pragma unroll
            for (int j = 0; j < 8; ++j) {
                float4 kv = *(const float4*)(Kb + (size_t)r * DMODEL + cb + j * 4);
                unsigned* dk = &Ks[r * KS_LD + cb + j * 4];
                dk[0] = f2tf(kv.x); dk[1] = f2tf(kv.y); dk[2] = f2tf(kv.z); dk[3] = f2tf(kv.w);
                float4 vv = *(const float4*)(Vb + (size_t)r * DMODEL + cb + j * 4);
                unsigned* dv = &Vs[r * VS_LD + cb + j * 4];
                dv[0] = f2tf(vv.x); dv[1] = f2tf(vv.y); dv[2] = f2tf(vv.z); dv[3] = f2tf(vv.w);
            }
        }
        __syncthreads();

        // S = Q @ K^T
        float s[8][4];
#pragma unroll
        for (int nt = 0; nt < 8; ++nt)
#pragma unroll
            for (int i = 0; i < 4; ++i) s[nt][i] = 0.f;

#pragma unroll
        for (int kk = 0; kk < 8; ++kk) {
#pragma unroll
            for (int nt = 0; nt < 8; ++nt) {
                int n = nt * 8 + (lane >> 2);
                unsigned b0 = Ks[n * KS_LD + kk * 8 + (lane & 3)];
                unsigned b1 = Ks[n * KS_LD + kk * 8 + (lane & 3) + 4];
                mma8(s[nt], qa[kk][0], qa[kk][1], qa[kk][2], qa[kk][3], b0, b1);
            }
        }

        // Online softmax (quad reduction: each row lives in 4 lanes)
        float mx0 = -INFINITY, mx1 = -INFINITY;
#pragma unroll
        for (int nt = 0; nt < 8; ++nt) {
            mx0 = fmaxf(mx0, fmaxf(s[nt][0], s[nt][1]));
            mx1 = fmaxf(mx1, fmaxf(s[nt][2], s[nt][3]));
        }
        mx0 = fmaxf(mx0, __shfl_xor_sync(0xffffffffu, mx0, 1));
        mx0 = fmaxf(mx0, __shfl_xor_sync(0xffffffffu, mx0, 2));
        mx1 = fmaxf(mx1, __shfl_xor_sync(0xffffffffu, mx1, 1));
        mx1 = fmaxf(mx1, __shfl_xor_sync(0xffffffffu, mx1, 2));

        float mn0 = fmaxf(m0, mx0), mn1 = fmaxf(m1, mx1);
        float cr0 = __expf(m0 - mn0), cr1 = __expf(m1 - mn1);
        float su0 = 0.f, su1 = 0.f;
#pragma unroll
        for (int nt = 0; nt < 8; ++nt) {
            s[nt][0] = __expf(s[nt][0] - mn0); su0 += s[nt][0];
            s[nt][1] = __expf(s[nt][1] - mn0); su0 += s[nt][1];
            s[nt][2] = __expf(s[nt][2] - mn1); su1 += s[nt][2];
            s[nt][3] = __expf(s[nt][3] - mn1); su1 += s[nt][3];
        }
        su0 += __shfl_xor_sync(0xffffffffu, su0, 1);
        su0 += __shfl_xor_sync(0xffffffffu, su0, 2);
        su1 += __shfl_xor_sync(0xffffffffu, su1, 1);
        su1 += __shfl_xor_sync(0xffffffffu, su1, 2);

        l0 = l0 * cr0 + su0; m0 = mn0;
        l1 = l1 * cr1 + su1; m1 = mn1;
#pragma unroll
        for (int nt = 0; nt < 8; ++nt) {
            o[nt][0] *= cr0; o[nt][1] *= cr0;
            o[nt][2] *= cr1; o[nt][3] *= cr1;
        }

        // Stage P into aliased Qs buffer (per-warp rows only -> syncwarp)
#pragma unroll
        for (int nt = 0; nt < 8; ++nt) {
            int r = wr + (lane >> 2);
            int cc = nt * 8 + 2 * (lane & 3);
            Ps[r * QS_LD + cc]           = f2tf(s[nt][0]);
            Ps[r * QS_LD + cc + 1]       = f2tf(s[nt][1]);
            Ps[(r + 8) * QS_LD + cc]     = f2tf(s[nt][2]);
            Ps[(r + 8) * QS_LD + cc + 1] = f2tf(s[nt][3]);
        }
        __syncwarp();

        // O += P @ V
#pragma unroll
        for (int kk = 0; kk < 8; ++kk) {
            int r = wr + (lane >> 2);
            int c = kk * 8 + (lane & 3);
            unsigned a0 = Ps[r * QS_LD + c];
            unsigned a1 = Ps[(r + 8) * QS_LD + c];
            unsigned a2 = Ps[r * QS_LD + c + 4];
            unsigned a3 = Ps[(r + 8) * QS_LD + c + 4];
#pragma unroll
            for (int nt = 0; nt < 8; ++nt) {
                int kr = kk * 8 + (lane & 3);
                int cc = nt * 8 + (lane >> 2);
                unsigned b0 = Vs[kr * VS_LD + cc];
                unsigned b1 = Vs[(kr + 4) * VS_LD + cc];
                mma8(o[nt], a0, a1, a2, a3, b0, b1);
            }
        }
        __syncthreads();
    }

    float inv0 = 1.f / l0, inv1 = 1.f / l1;
    float* Ob = Og + ((size_t)(b * SEQ + q0)) * DMODEL + h * DK;
#pragma unroll
    for (int nt = 0; nt < 8; ++nt) {
        int r = wr + (lane >> 2);
        int cc = nt * 8 + 2 * (lane & 3);
        *(float2*)(Ob + (size_t)r * DMODEL + cc) =
            make_float2(o[nt][0] * inv0, o[nt][1] * inv0);
        *(float2*)(Ob + (size_t)(r + 8) * DMODEL + cc) =
            make_float2(o[nt][2] * inv1, o[nt][3] * inv1);
    }
}

// ---------------------------------------------------------------------------
extern "C" void kernel_launch(void* const* d_in, const int* in_sizes, int n_in,
                              void* d_out, int out_size)
{
    const float* x  = (const float*)d_in[0];
    const float* Wq = (const float*)d_in[1];
    const float* bq = (const float*)d_in[2];
    const float* Wk = (const float*)d_in[3];
    const float* bk = (const float*)d_in[4];
    const float* Wv = (const float*)d_in[5];
    const float* bv = (const float*)d_in[6];
    const float* Wo = (const float*)d_in[7];
    const float* bo = (const float*)d_in[8];
    float* out = (float*)d_out;

    float *q, *k, *v, *a;
    cudaGetSymbolAddress((void**)&q, g_Q);
    cudaGetSymbolAddress((void**)&k, g_K);
    cudaGetSymbolAddress((void**)&v, g_V);
    cudaGetSymbolAddress((void**)&a, g_A);

    cudaFuncSetAttribute(attn_tc,
                         cudaFuncAttributeMaxDynamicSharedMemorySize, ATT_SMEM);

    dim3 gemmGrid(DMODEL / 128, MROWS / 128);   // (8, 32)
    gemm_tc<<<gemmGrid, 256>>>(x, Wq, bq, q, MROWS, DMODEL, DMODEL);
    gemm_tc<<<gemmGrid, 256>>>(x, Wk, bk, k, MROWS, DMODEL, DMODEL);
    gemm_tc<<<gemmGrid, 256>>>(x, Wv, bv, v, MROWS, DMODEL, DMODEL);

    dim3 attGrid(SEQ / 64, BATCH * NHEAD);      // (32, 32)
    attn_tc<<<attGrid, 128, ATT_SMEM>>>(q, k, v, a);

    gemm_tc<<<gemmGrid, 256>>>(a, Wo, bo, out, MROWS, DMODEL, DMODEL);
}